// round 13
// baseline (speedup 1.0000x reference)
#include <cuda_runtime.h>
#include <math.h>
#include <stdint.h>

// RotorQuantMSE — R13: R12 dual-row-stream kernel with the stream pair packed
// into f32x2 (Blackwell FFMA2) for all rotation/quant FMA chains. Magic-constant
// round-to-nearest replaces ceilf (equal except exact-midpoint band). Clamp and
// dequant scalar on halves; selects/shuffles unchanged.

#define D 768
#define NBLK 444    // 148 SMs * 3 blocks — uniform wave at ~98 regs

__device__ __forceinline__ uint64_t pk2(float lo, float hi) {
    uint64_t r; asm("mov.b64 %0, {%1, %2};" : "=l"(r) : "f"(lo), "f"(hi)); return r;
}
__device__ __forceinline__ void upk2(uint64_t v, float& lo, float& hi) {
    asm("mov.b64 {%0, %1}, %2;" : "=f"(lo), "=f"(hi) : "l"(v));
}
__device__ __forceinline__ uint64_t fma2(uint64_t a, uint64_t b, uint64_t c) {
    uint64_t d; asm("fma.rn.f32x2 %0, %1, %2, %3;" : "=l"(d) : "l"(a), "l"(b), "l"(c)); return d;
}
__device__ __forceinline__ uint64_t mul2(uint64_t a, uint64_t b) {
    uint64_t d; asm("mul.rn.f32x2 %0, %1, %2;" : "=l"(d) : "l"(a), "l"(b)); return d;
}
__device__ __forceinline__ uint64_t add2(uint64_t a, uint64_t b) {
    uint64_t d; asm("add.rn.f32x2 %0, %1, %2;" : "=l"(d) : "l"(a), "l"(b)); return d;
}

__device__ __forceinline__ void rotor_apply(
    float r0, float b1, float b2, float b3,
    float v1, float v2, float v3,
    float& o1, float& o2, float& o3)
{
    float t1 = fmaf(r0, v1, fmaf(b1, v2,  b2 * v3));
    float t2 = fmaf(r0, v2, fmaf(-b1, v1, b3 * v3));
    float t3 = fmaf(r0, v3, fmaf(-b2, v1, -b3 * v2));
    float t7 = fmaf(b1, v3, fmaf(-b2, v2,  b3 * v1));
    o1 = fmaf(r0, t1, fmaf( b1, t2, fmaf( b2, t3,  b3 * t7)));
    o2 = fmaf(r0, t2, fmaf(-b1, t1, fmaf( b3, t3, -b2 * t7)));
    o3 = fmaf(r0, t3, fmaf(-b2, t1, fmaf(-b3, t2,  b1 * t7)));
}

__device__ __forceinline__ void build_mat(const float* __restrict__ rp, float M[9])
{
    float r0 = __ldg(rp + 0);
    float4 bv = __ldg(reinterpret_cast<const float4*>(rp + 4));
    float b1 = bv.x, b2 = bv.y, b3 = bv.z;
    rotor_apply(r0, b1, b2, b3, 1.f, 0.f, 0.f, M[0], M[3], M[6]);
    rotor_apply(r0, b1, b2, b3, 0.f, 1.f, 0.f, M[1], M[4], M[7]);
    rotor_apply(r0, b1, b2, b3, 0.f, 0.f, 1.f, M[2], M[5], M[8]);
}

__global__ void __launch_bounds__(192)
rotor_quant_kernel(const float* __restrict__ x,
                   const float* __restrict__ rotors,
                   float* __restrict__ xhat,
                   float* __restrict__ idx_out,
                   float* __restrict__ norms_out,
                   int N)
{
    const int w = threadIdx.x >> 5;
    const int l = threadIdx.x & 31;
    const int p0 = 128 * w + 4 * l;
    const int m  = p0 % 3;
    const int gA = p0 / 3;
    const int f4 = 32 * w + l;
    const int HALF = N >> 1;

    // packed (duplicated) matrix coefficients
    float MA[9], MB[9];
    build_mat(rotors + (size_t)gA * 8, MA);
    build_mat(rotors + (size_t)(gA + 1) * 8, MB);
    uint64_t MAp[9], MBp[9];
    #pragma unroll
    for (int k = 0; k < 9; k++) { MAp[k] = pk2(MA[k], MA[k]); MBp[k] = pk2(MB[k], MB[k]); }

    const bool needPrev = (l == 0)  && ((128 * w) % 3 != 0);
    const bool needNext = (l == 31) && ((128 * (w + 1)) % 3 != 0);
    const float step = 2.0f / 15.0f;
    const uint64_t C75  = pk2(7.5f, 7.5f);
    const uint64_t MAGp = pk2(12582912.0f, 12582912.0f);    // 1.5 * 2^23
    const uint64_t NMAGp = pk2(-12582912.0f, -12582912.0f);

    __shared__ __align__(16) float spart[2][2][8];

    int r1 = blockIdx.x;
    float4 aA = make_float4(0,0,0,0), aB = make_float4(0,0,0,0);
    float2 pvA = make_float2(0,0), nxA = make_float2(0,0);
    float2 pvB = make_float2(0,0), nxB = make_float2(0,0);
    if (r1 < HALF) {
        const float* xr = x + (size_t)r1 * D;
        aA = __ldg(reinterpret_cast<const float4*>(xr) + f4);
        if (needPrev) pvA = __ldg(reinterpret_cast<const float2*>(xr + 128 * w - 2));
        if (needNext) nxA = __ldg(reinterpret_cast<const float2*>(xr + 128 * (w + 1)));
        const float* xs = xr + (size_t)HALF * D;
        aB = __ldg(reinterpret_cast<const float4*>(xs) + f4);
        if (needPrev) pvB = __ldg(reinterpret_cast<const float2*>(xs + 128 * w - 2));
        if (needNext) nxB = __ldg(reinterpret_cast<const float2*>(xs + 128 * (w + 1)));
    }

    int buf = 0;
    for (; r1 < HALF; r1 += NBLK) {
        const int r2 = r1 + HALF;

        float s1 = fmaf(aA.x, aA.x, fmaf(aA.y, aA.y, fmaf(aA.z, aA.z, aA.w * aA.w)));
        float s2 = fmaf(aB.x, aB.x, fmaf(aB.y, aB.y, fmaf(aB.z, aB.z, aB.w * aB.w)));
        #pragma unroll
        for (int o = 16; o; o >>= 1) {
            s1 += __shfl_xor_sync(0xffffffffu, s1, o);
            s2 += __shfl_xor_sync(0xffffffffu, s2, o);
        }
        if (l == 0) { spart[buf][0][w] = s1; spart[buf][1][w] = s2; }

        const int n1 = r1 + NBLK;
        float4 aA2 = make_float4(0,0,0,0), aB2 = make_float4(0,0,0,0);
        float2 pvA2 = make_float2(0,0), nxA2 = make_float2(0,0);
        float2 pvB2 = make_float2(0,0), nxB2 = make_float2(0,0);
        if (n1 < HALF) {
            const float* xr = x + (size_t)n1 * D;
            aA2 = __ldg(reinterpret_cast<const float4*>(xr) + f4);
            if (needPrev) pvA2 = __ldg(reinterpret_cast<const float2*>(xr + 128 * w - 2));
            if (needNext) nxA2 = __ldg(reinterpret_cast<const float2*>(xr + 128 * (w + 1)));
            const float* xs = xr + (size_t)HALF * D;
            aB2 = __ldg(reinterpret_cast<const float4*>(xs) + f4);
            if (needPrev) pvB2 = __ldg(reinterpret_cast<const float2*>(xs + 128 * w - 2));
            if (needNext) nxB2 = __ldg(reinterpret_cast<const float2*>(xs + 128 * (w + 1)));
        }

        __syncthreads();
        float4 u4 = *reinterpret_cast<float4*>(spart[buf][0]);
        float2 u2 = *reinterpret_cast<float2*>(spart[buf][0] + 4);
        float4 v4 = *reinterpret_cast<float4*>(spart[buf][1]);
        float2 v2 = *reinterpret_cast<float2*>(spart[buf][1] + 4);
        buf ^= 1;
        const float nrm1 = fmaxf(sqrtf(u4.x + u4.y + u4.z + u4.w + u2.x + u2.y), 1e-8f);
        const float nrm2 = fmaxf(sqrtf(v4.x + v4.y + v4.z + v4.w + v2.x + v2.y), 1e-8f);
        const uint64_t invp = pk2(1.0f / nrm1, 1.0f / nrm2);
        const float qs1 = step * nrm1, qb1 = -nrm1;
        const float qs2 = step * nrm2, qb2 = -nrm2;

        // neighbor exchange + input selects, scalar, both streams
        float e0a = __shfl_up_sync(0xffffffffu, aA.z, 1);
        float e1a = __shfl_up_sync(0xffffffffu, aA.w, 1);
        float e6a = __shfl_down_sync(0xffffffffu, aA.x, 1);
        float e7a = __shfl_down_sync(0xffffffffu, aA.y, 1);
        float e0b = __shfl_up_sync(0xffffffffu, aB.z, 1);
        float e1b = __shfl_up_sync(0xffffffffu, aB.w, 1);
        float e6b = __shfl_down_sync(0xffffffffu, aB.x, 1);
        float e7b = __shfl_down_sync(0xffffffffu, aB.y, 1);
        if (l == 0)  { e0a = pvA.x; e1a = pvA.y; e0b = pvB.x; e1b = pvB.y; }
        if (l == 31) { e6a = nxA.x; e7a = nxA.y; e6b = nxB.x; e7b = nxB.y; }

        float vA0a = (m==0)?aA.x:(m==1)?e1a:e0a;
        float vA1a = (m==0)?aA.y:(m==1)?aA.x:e1a;
        float vA2a = (m==0)?aA.z:(m==1)?aA.y:aA.x;
        float vB0a = (m==0)?aA.w:(m==1)?aA.z:aA.y;
        float vB1a = (m==0)?e6a:(m==1)?aA.w:aA.z;
        float vB2a = (m==0)?e7a:(m==1)?e6a:aA.w;
        float vA0b = (m==0)?aB.x:(m==1)?e1b:e0b;
        float vA1b = (m==0)?aB.y:(m==1)?aB.x:e1b;
        float vA2b = (m==0)?aB.z:(m==1)?aB.y:aB.x;
        float vB0b = (m==0)?aB.w:(m==1)?aB.z:aB.y;
        float vB1b = (m==0)?e6b:(m==1)?aB.w:aB.z;
        float vB2b = (m==0)?e7b:(m==1)?e6b:aB.w;

        // pack stream pairs
        uint64_t vA0 = pk2(vA0a, vA0b), vA1 = pk2(vA1a, vA1b), vA2 = pk2(vA2a, vA2b);
        uint64_t vB0 = pk2(vB0a, vB0b), vB1 = pk2(vB1a, vB1b), vB2 = pk2(vB2a, vB2b);

        // forward rotation (packed), then *inv, then u' = (t+1)*7.5 as fma(t,7.5,7.5)
        uint64_t yA0 = fma2(MAp[0], vA0, fma2(MAp[1], vA1, mul2(MAp[2], vA2)));
        uint64_t yA1 = fma2(MAp[3], vA0, fma2(MAp[4], vA1, mul2(MAp[5], vA2)));
        uint64_t yA2 = fma2(MAp[6], vA0, fma2(MAp[7], vA1, mul2(MAp[8], vA2)));
        uint64_t yB0 = fma2(MBp[0], vB0, fma2(MBp[1], vB1, mul2(MBp[2], vB2)));
        uint64_t yB1 = fma2(MBp[3], vB0, fma2(MBp[4], vB1, mul2(MBp[5], vB2)));
        uint64_t yB2 = fma2(MBp[6], vB0, fma2(MBp[7], vB1, mul2(MBp[8], vB2)));

        uint64_t uA0 = fma2(mul2(yA0, invp), C75, C75);
        uint64_t uA1 = fma2(mul2(yA1, invp), C75, C75);
        uint64_t uA2 = fma2(mul2(yA2, invp), C75, C75);
        uint64_t uB0 = fma2(mul2(yB0, invp), C75, C75);
        uint64_t uB1 = fma2(mul2(yB1, invp), C75, C75);
        uint64_t uB2 = fma2(mul2(yB2, invp), C75, C75);

        // round-to-nearest via magic add (u' in [0,15] +/- eps)
        uint64_t kA0 = add2(add2(uA0, MAGp), NMAGp);
        uint64_t kA1 = add2(add2(uA1, MAGp), NMAGp);
        uint64_t kA2 = add2(add2(uA2, MAGp), NMAGp);
        uint64_t kB0 = add2(add2(uB0, MAGp), NMAGp);
        uint64_t kB1 = add2(add2(uB1, MAGp), NMAGp);
        uint64_t kB2 = add2(add2(uB2, MAGp), NMAGp);

        // unpack, clamp, dequant (scalar), repack q
        float fA0a,fA0b,fA1a,fA1b,fA2a,fA2b,fB0a,fB0b,fB1a,fB1b,fB2a,fB2b;
        upk2(kA0,fA0a,fA0b); upk2(kA1,fA1a,fA1b); upk2(kA2,fA2a,fA2b);
        upk2(kB0,fB0a,fB0b); upk2(kB1,fB1a,fB1b); upk2(kB2,fB2a,fB2b);
        fA0a=fminf(fmaxf(fA0a,0.f),15.f); fA0b=fminf(fmaxf(fA0b,0.f),15.f);
        fA1a=fminf(fmaxf(fA1a,0.f),15.f); fA1b=fminf(fmaxf(fA1b,0.f),15.f);
        fA2a=fminf(fmaxf(fA2a,0.f),15.f); fA2b=fminf(fmaxf(fA2b,0.f),15.f);
        fB0a=fminf(fmaxf(fB0a,0.f),15.f); fB0b=fminf(fmaxf(fB0b,0.f),15.f);
        fB1a=fminf(fmaxf(fB1a,0.f),15.f); fB1b=fminf(fmaxf(fB1b,0.f),15.f);
        fB2a=fminf(fmaxf(fB2a,0.f),15.f); fB2b=fminf(fmaxf(fB2b,0.f),15.f);

        uint64_t qA0 = pk2(fmaf(fA0a,qs1,qb1), fmaf(fA0b,qs2,qb2));
        uint64_t qA1 = pk2(fmaf(fA1a,qs1,qb1), fmaf(fA1b,qs2,qb2));
        uint64_t qA2 = pk2(fmaf(fA2a,qs1,qb1), fmaf(fA2b,qs2,qb2));
        uint64_t qB0 = pk2(fmaf(fB0a,qs1,qb1), fmaf(fB0b,qs2,qb2));
        uint64_t qB1 = pk2(fmaf(fB1a,qs1,qb1), fmaf(fB1b,qs2,qb2));
        uint64_t qB2 = pk2(fmaf(fB2a,qs1,qb1), fmaf(fB2b,qs2,qb2));

        // inverse rotation = M^T (packed), result pre-scaled by nrm
        uint64_t hA0 = fma2(MAp[0], qA0, fma2(MAp[3], qA1, mul2(MAp[6], qA2)));
        uint64_t hA1 = fma2(MAp[1], qA0, fma2(MAp[4], qA1, mul2(MAp[7], qA2)));
        uint64_t hA2 = fma2(MAp[2], qA0, fma2(MAp[5], qA1, mul2(MAp[8], qA2)));
        uint64_t hB0 = fma2(MBp[0], qB0, fma2(MBp[3], qB1, mul2(MBp[6], qB2)));
        uint64_t hB1 = fma2(MBp[1], qB0, fma2(MBp[4], qB1, mul2(MBp[7], qB2)));
        uint64_t hB2 = fma2(MBp[2], qB0, fma2(MBp[5], qB1, mul2(MBp[8], qB2)));

        float hA0a,hA0b,hA1a,hA1b,hA2a,hA2b,hB0a,hB0b,hB1a,hB1b,hB2a,hB2b;
        upk2(hA0,hA0a,hA0b); upk2(hA1,hA1a,hA1b); upk2(hA2,hA2a,hA2b);
        upk2(hB0,hB0a,hB0b); upk2(hB1,hB1a,hB1b); upk2(hB2,hB2a,hB2b);

        float4 oh1, oi1, oh2, oi2;
        oh1.x=(m==0)?hA0a:(m==1)?hA1a:hA2a;  oh1.y=(m==0)?hA1a:(m==1)?hA2a:hB0a;
        oh1.z=(m==0)?hA2a:(m==1)?hB0a:hB1a;  oh1.w=(m==0)?hB0a:(m==1)?hB1a:hB2a;
        oh2.x=(m==0)?hA0b:(m==1)?hA1b:hA2b;  oh2.y=(m==0)?hA1b:(m==1)?hA2b:hB0b;
        oh2.z=(m==0)?hA2b:(m==1)?hB0b:hB1b;  oh2.w=(m==0)?hB0b:(m==1)?hB1b:hB2b;
        oi1.x=(m==0)?fA0a:(m==1)?fA1a:fA2a;  oi1.y=(m==0)?fA1a:(m==1)?fA2a:fB0a;
        oi1.z=(m==0)?fA2a:(m==1)?fB0a:fB1a;  oi1.w=(m==0)?fB0a:(m==1)?fB1a:fB2a;
        oi2.x=(m==0)?fA0b:(m==1)?fA1b:fA2b;  oi2.y=(m==0)?fA1b:(m==1)?fA2b:fB0b;
        oi2.z=(m==0)?fA2b:(m==1)?fB0b:fB1b;  oi2.w=(m==0)?fB0b:(m==1)?fB1b:fB2b;

        reinterpret_cast<float4*>(xhat + (size_t)r1 * D)[f4] = oh1;
        reinterpret_cast<float4*>(xhat + (size_t)r2 * D)[f4] = oh2;
        if (idx_out) {
            reinterpret_cast<float4*>(idx_out + (size_t)r1 * D)[f4] = oi1;
            reinterpret_cast<float4*>(idx_out + (size_t)r2 * D)[f4] = oi2;
        }
        if (threadIdx.x == 0 && norms_out) {
            norms_out[r1] = nrm1;
            norms_out[r2] = nrm2;
        }

        aA = aA2; pvA = pvA2; nxA = nxA2;
        aB = aB2; pvB = pvB2; nxB = nxB2;
    }
}

extern "C" void kernel_launch(void* const* d_in, const int* in_sizes, int n_in,
                              void* d_out, int out_size)
{
    const float* x      = (const float*)d_in[0];   // [N, d]
    const float* rotors = (const float*)d_in[2];   // [G, 8]

    const int G = in_sizes[2] / 8;        // 256
    const int d = 3 * G;                  // 768
    const int N = in_sizes[0] / d;        // 8192

    float* out   = (float*)d_out;
    float* xhat  = out;
    float* idxp  = nullptr;
    float* normp = nullptr;
    const long nd = (long)N * d;
    if ((long)out_size >= 2 * nd)     idxp  = out + nd;
    if ((long)out_size >= 2 * nd + N) normp = out + 2 * nd;

    rotor_quant_kernel<<<NBLK, 192>>>(x, rotors, xhat, idxp, normp, N);
}